// round 6
// baseline (speedup 1.0000x reference)
#include <cuda_runtime.h>
#include <cuda_bf16.h>
#include <math.h>
#include <stdint.h>

// ArcFace loss. B=512, F=128, C=100000.
// Persistent CTAs, A resident in smem (converted once), B double-buffered
// per tile (BN=128), 1 barrier per tile, epilogue writes partial row sums
// straight to gmem. target is i32-or-i64 (sniffed).

#define FF 128
#define BB 512
#define BN 128
#define NCTA 148

__device__ float g_part[1600 * 512];  // [tileslot = bx*2+wn][row]
__device__ float g_margin[BB];
__device__ float g_adj[BB];
__device__ float g_rowv[BB];

// smem: A 512 rows x 272B (resident) | B 2 bufs x 128 k-rows x 272B
#define ASTRIDE 272
#define SM_A    0
#define ASZ_ALL (512 * ASTRIDE)          // 139264
#define BSTRIDE 272
#define BSZ     (128 * BSTRIDE)          // 34816
#define SM_B    ASZ_ALL                  // 139264
#define SM_TOTAL (SM_B + 2 * BSZ)        // 208896

__device__ __forceinline__ uint32_t smem_u32(const void* p) {
    uint32_t a;
    asm("{ .reg .u64 t; cvta.to.shared.u64 t, %1; cvt.u32.u64 %0, t; }"
        : "=r"(a) : "l"(p));
    return a;
}
__device__ __forceinline__ void ldsm4(uint32_t* r, uint32_t addr) {
    asm volatile("ldmatrix.sync.aligned.m8n8.x4.shared.b16 {%0,%1,%2,%3}, [%4];"
                 : "=r"(r[0]), "=r"(r[1]), "=r"(r[2]), "=r"(r[3]) : "r"(addr));
}
__device__ __forceinline__ void ldsm4t(uint32_t* r, uint32_t addr) {
    asm volatile("ldmatrix.sync.aligned.m8n8.x4.trans.shared.b16 {%0,%1,%2,%3}, [%4];"
                 : "=r"(r[0]), "=r"(r[1]), "=r"(r[2]), "=r"(r[3]) : "r"(addr));
}
__device__ __forceinline__ void mma_bf16(float* d, const uint32_t* a,
                                         uint32_t b0, uint32_t b1) {
    asm volatile(
        "mma.sync.aligned.m16n8k16.row.col.f32.bf16.bf16.f32 "
        "{%0,%1,%2,%3}, {%4,%5,%6,%7}, {%8,%9}, {%0,%1,%2,%3};"
        : "+f"(d[0]), "+f"(d[1]), "+f"(d[2]), "+f"(d[3])
        : "r"(a[0]), "r"(a[1]), "r"(a[2]), "r"(a[3]), "r"(b0), "r"(b1));
}
__device__ __forceinline__ uint32_t pack_bf16x2(float lo, float hi) {
    __nv_bfloat162 p = __floats2bfloat162_rn(lo, hi);
    return *(uint32_t*)&p;
}
__device__ __forceinline__ float fast_exp(float x) {   // FMA-pipe exp
    float z = x * 1.4426950408889634f;
    float n = rintf(z);
    float f = z - n;
    float p = 1.5403530393381606e-4f;
    p = fmaf(p, f, 1.3333558146428443e-3f);
    p = fmaf(p, f, 9.6181291076284770e-3f);
    p = fmaf(p, f, 5.5504108664821580e-2f);
    p = fmaf(p, f, 2.4022650695910070e-1f);
    p = fmaf(p, f, 6.9314718055994530e-1f);
    p = fmaf(p, f, 1.0f);
    return __int_as_float(__float_as_int(p) + ((int)n << 23));
}
__device__ __forceinline__ int load_target(const void* tptr, int b, int C) {
    const int* p = (const int*)tptr;
    bool is64 = ((p[1] | p[3] | p[5] | p[7] | p[9]) == 0);
    long long t = is64 ? ((const long long*)tptr)[b] : (long long)p[b];
    if (t < 0) t = 0;
    if (t >= C) t = C - 1;
    return (int)t;
}

// Load 64 k-rows (half h) of the B tile at col base c0 into buffer buf.
// Layout [k][n] bf16, row stride 272B, 16B-chunk XOR swizzle by (k>>3)&1.
// 4 float4 LDG + 4 uint2 STS per thread.
__device__ __forceinline__ void load_B_half(const float* __restrict__ w,
                                            char* smem, int buf, int h,
                                            int c0, int C, int tid) {
    const float4* w4 = (const float4*)w;
    char* base = smem + SM_B + buf * BSZ;
    #pragma unroll
    for (int i = 0; i < 4; i++) {
        int idx = i * 512 + tid;              // 0..2047
        int k = h * 64 + (idx >> 5);          // tile-local k row
        int cq = idx & 31;                    // col quad
        int c = c0 + cq * 4;
        float4 v = make_float4(0.f, 0.f, 0.f, 0.f);
        if (c < C)                            // C % 4 == 0 -> all-or-nothing
            v = w4[((size_t)k * (size_t)C + (size_t)c) >> 2];
        uint2 pk;
        pk.x = pack_bf16x2(v.x, v.y);
        pk.y = pack_bf16x2(v.z, v.w);
        uint32_t byte = (uint32_t)(cq * 8) ^ (uint32_t)(((k >> 3) & 1) << 4);
        *(uint2*)(base + k * BSTRIDE + byte) = pk;
    }
}

// ================= persistent fused kernel =================
__global__ void __launch_bounds__(512, 1)
fused_kernel(const float* __restrict__ feat, const float* __restrict__ w,
             const void* __restrict__ target, int C, int NT) {
    extern __shared__ char smem[];
    const int tid  = threadIdx.x;
    const int wid  = tid >> 5;
    const int lane = tid & 31;
    const int bid  = blockIdx.x;
    const int wm   = wid >> 1;            // warp row group 0..7 (32 rows)
    const int wn   = wid & 1;             // warp col group 0..1 (64 cols)
    const uint32_t sb = smem_u32(smem);

    // ---- prologue: A (all 512 rows) converted once + first B tile + aux ----
    {
        const float4* f4 = (const float4*)feat;
        #pragma unroll 4
        for (int i = 0; i < 32; i++) {
            int idx = i * 512 + tid;          // 0..16383
            int r = idx >> 5, kq = idx & 31;
            float4 v = f4[r * 32 + kq];
            uint2 pk;
            pk.x = pack_bf16x2(v.x, v.y);
            pk.y = pack_bf16x2(v.z, v.w);
            *(uint2*)(smem + SM_A + r * ASTRIDE + kq * 8) = pk;
        }
    }
    load_B_half(w, smem, 0, 0, bid * BN, C, tid);
    load_B_half(w, smem, 0, 1, bid * BN, C, tid);

    // aux: exact-fp32 target-column math, rows bid*4..bid*4+3 (CTAs 0..127)
    if (bid < 128 && wid < 4) {
        int b = bid * 4 + wid;
        int t = load_target(target, b, C);
        float fsq = 0.f, wsq = 0.f, dot = 0.f;
        #pragma unroll
        for (int q = 0; q < 4; q++) {
            int f = lane + q * 32;
            float fv = feat[b * FF + f];
            float wv = w[(size_t)f * (size_t)C + (size_t)t];
            fsq = fmaf(fv, fv, fsq);
            wsq = fmaf(wv, wv, wsq);
            dot = fmaf(fv, wv, dot);
        }
        const unsigned msk = 0xffffffffu;
        #pragma unroll
        for (int o = 16; o > 0; o >>= 1) {
            fsq += __shfl_down_sync(msk, fsq, o);
            wsq += __shfl_down_sync(msk, wsq, o);
            dot += __shfl_down_sync(msk, dot, o);
        }
        if (lane == 0) {
            float modulus = sqrtf(fsq) * sqrtf(wsq);
            float ct = dot / (modulus * 1.01f);
            ct = fminf(1.0f, fmaxf(-1.0f, ct));
            float ml = modulus * cosf(acosf(ct) + 0.5f);  // ANGLE=0.5
            g_margin[b] = ml;
            g_adj[b] = expf(ml) - expf(dot);
        }
    }
    __syncthreads();

    // per-lane ldmatrix bases (mapping identical to round-5 proven layout)
    const uint32_t a_lb = (uint32_t)((wm * 32 + (lane & 15)) * ASTRIDE
                                     + ((lane >> 4) << 4));
    const uint32_t b_lb = (uint32_t)((((lane >> 3) & 1) * 8 + (lane & 7)) * BSTRIDE
                          + (((uint32_t)(wn * 128 + ((lane >> 4) << 4)))
                             ^ (uint32_t)(((lane >> 3) & 1) << 4)));

    int cur = 0;
    for (int bx = bid; bx < NT; bx += NCTA) {
        const bool have_next = (bx + NCTA) < NT;
        const int nc0 = (bx + NCTA) * BN;
        const uint32_t bbase = sb + SM_B + cur * BSZ;

        for (int mc = 0; mc < 2; mc++) {       // 256-row halves of A
            if (have_next)                      // prefetch half of next B tile
                load_B_half(w, smem, cur ^ 1, mc, nc0, C, tid);

            const uint32_t abase = sb + SM_A + mc * (256 * ASTRIDE);

            float acc[2][8][4];
            #pragma unroll
            for (int mi = 0; mi < 2; mi++)
                #pragma unroll
                for (int j = 0; j < 8; j++)
                    #pragma unroll
                    for (int q = 0; q < 4; q++) acc[mi][j][q] = 0.0f;

            #pragma unroll
            for (int ks = 0; ks < 8; ks++) {
                uint32_t a[2][4];
                ldsm4(a[0], abase + a_lb + ks * 32);
                ldsm4(a[1], abase + a_lb + 16 * ASTRIDE + ks * 32);
                #pragma unroll
                for (int np = 0; np < 4; np++) {
                    uint32_t bfr[4];
                    ldsm4t(bfr, bbase + b_lb + ks * 16 * BSTRIDE + np * 32);
                    #pragma unroll
                    for (int mi = 0; mi < 2; mi++) {
                        mma_bf16(acc[mi][np * 2 + 0], a[mi], bfr[0], bfr[1]);
                        mma_bf16(acc[mi][np * 2 + 1], a[mi], bfr[2], bfr[3]);
                    }
                }
            }

            // epilogue: hybrid exp + warp row-sums -> direct STG (no barrier)
            const unsigned msk = 0xffffffffu;
            float* slot = &g_part[(size_t)(bx * 2 + wn) * 512];
            #pragma unroll
            for (int mi = 0; mi < 2; mi++) {
                float s0 = 0.f, s1 = 0.f;
                #pragma unroll
                for (int j = 0; j < 8; j++) {
                    s0 += __expf(acc[mi][j][0]);      // MUFU half
                    s0 += __expf(acc[mi][j][1]);
                    s1 += fast_exp(acc[mi][j][2]);    // FMA half
                    s1 += fast_exp(acc[mi][j][3]);
                }
                s0 += __shfl_xor_sync(msk, s0, 1);
                s0 += __shfl_xor_sync(msk, s0, 2);
                s1 += __shfl_xor_sync(msk, s1, 1);
                s1 += __shfl_xor_sync(msk, s1, 2);
                if ((lane & 3) == 0) {
                    int g = lane >> 2;
                    int grow = mc * 256 + wm * 32 + mi * 16 + g;
                    slot[grow] = s0;          // rows g   .. g+7  partials
                    slot[grow + 8] = s1;      // rows g+8 .. g+15 partials
                }
            }
        }
        __syncthreads();                      // B buffer swap protection
        cur ^= 1;
    }
}

// ================= finalize 1: per-row value =================
__global__ void finalize1_kernel(int NT2, float pad) {
    int row = blockIdx.x;        // 0..511
    int j = threadIdx.x;         // 0..127
    float s = 0.f;
    for (int t = j; t < NT2; t += 128)        // fixed order -> deterministic
        s += g_part[(size_t)t * 512 + row];
    __shared__ float red[128];
    red[j] = s;
    __syncthreads();
    #pragma unroll
    for (int o = 64; o > 0; o >>= 1) {
        if (j < o) red[j] += red[j + o];
        __syncthreads();
    }
    if (j == 0) {
        float down = red[0] - pad + g_adj[row];
        g_rowv[row] = logf(down) - g_margin[row];
    }
}

// ================= finalize 2: scalar =================
__global__ void finalize2_kernel(float* __restrict__ out) {
    int b = threadIdx.x;         // 0..511
    __shared__ float red[BB];
    red[b] = g_rowv[b];
    __syncthreads();
    #pragma unroll
    for (int o = BB / 2; o > 0; o >>= 1) {
        if (b < o) red[b] += red[b + o];
        __syncthreads();
    }
    if (b == 0) out[0] = red[0] / (float)BB;
}

// ================= launch =================
extern "C" void kernel_launch(void* const* d_in, const int* in_sizes, int n_in,
                              void* d_out, int out_size) {
    const float* feat = (const float*)d_in[0];
    const float* w    = (const float*)d_in[1];
    const void*  target = d_in[2];
    float* out = (float*)d_out;

    int C  = in_sizes[1] / FF;               // 100000
    int NT = (C + BN - 1) / BN;              // 782
    float pad = (float)(NT * BN - C);        // 96

    cudaFuncSetAttribute(fused_kernel,
                         cudaFuncAttributeMaxDynamicSharedMemorySize, SM_TOTAL);

    fused_kernel<<<NCTA, 512, SM_TOTAL>>>(feat, w, target, C, NT);
    finalize1_kernel<<<BB, 128>>>(2 * NT, pad);
    finalize2_kernel<<<1, BB>>>(out);
}

// round 7
// speedup vs baseline: 1.3547x; 1.3547x over previous
#include <cuda_runtime.h>
#include <cuda_bf16.h>
#include <math.h>
#include <stdint.h>

// ArcFace loss. B=512, F=128, C=100000.
// Round-5 structure (70.4us) + all-FMA exp (MUFU was ~45us busy = hidden
// co-bottleneck) + barrier-free direct-STG epilogue.

#define FF 128
#define BB 512
#define BN 256
#define NCTA 148

__device__ float g_part[1600 * 512];  // [slot = bx*4 + wn][row]
__device__ float g_margin[BB];
__device__ float g_adj[BB];
__device__ float g_rowv[BB];

// smem: B 2x(128 k-rows x 528B) | A 2x(128 rows x 272B)
#define BSTRIDE 528
#define BSZ     (128 * BSTRIDE)      // 67584
#define ASTRIDE 272
#define ASZ     (128 * ASTRIDE)      // 34816
#define SM_B    0
#define SM_A    (2 * BSZ)            // 135168
#define SM_TOTAL (SM_A + 2 * ASZ)    // 204800

__device__ __forceinline__ uint32_t smem_u32(const void* p) {
    uint32_t a;
    asm("{ .reg .u64 t; cvta.to.shared.u64 t, %1; cvt.u32.u64 %0, t; }"
        : "=r"(a) : "l"(p));
    return a;
}
__device__ __forceinline__ void ldsm4(uint32_t* r, uint32_t addr) {
    asm volatile("ldmatrix.sync.aligned.m8n8.x4.shared.b16 {%0,%1,%2,%3}, [%4];"
                 : "=r"(r[0]), "=r"(r[1]), "=r"(r[2]), "=r"(r[3]) : "r"(addr));
}
__device__ __forceinline__ void ldsm4t(uint32_t* r, uint32_t addr) {
    asm volatile("ldmatrix.sync.aligned.m8n8.x4.trans.shared.b16 {%0,%1,%2,%3}, [%4];"
                 : "=r"(r[0]), "=r"(r[1]), "=r"(r[2]), "=r"(r[3]) : "r"(addr));
}
__device__ __forceinline__ void mma_bf16(float* d, const uint32_t* a,
                                         uint32_t b0, uint32_t b1) {
    asm volatile(
        "mma.sync.aligned.m16n8k16.row.col.f32.bf16.bf16.f32 "
        "{%0,%1,%2,%3}, {%4,%5,%6,%7}, {%8,%9}, {%0,%1,%2,%3};"
        : "+f"(d[0]), "+f"(d[1]), "+f"(d[2]), "+f"(d[3])
        : "r"(a[0]), "r"(a[1]), "r"(a[2]), "r"(a[3]), "r"(b0), "r"(b1));
}
__device__ __forceinline__ uint32_t pack_bf16x2(float lo, float hi) {
    __nv_bfloat162 p = __floats2bfloat162_rn(lo, hi);
    return *(uint32_t*)&p;
}
// FMA-pipe exp: 2^(x*log2e), deg-6 Taylor on f in [-0.5,0.5]. fast_exp(0)==1.
__device__ __forceinline__ float fast_exp(float x) {
    float z = x * 1.4426950408889634f;
    float n = rintf(z);
    float f = z - n;
    float p = 1.5403530393381606e-4f;
    p = fmaf(p, f, 1.3333558146428443e-3f);
    p = fmaf(p, f, 9.6181291076284770e-3f);
    p = fmaf(p, f, 5.5504108664821580e-2f);
    p = fmaf(p, f, 2.4022650695910070e-1f);
    p = fmaf(p, f, 6.9314718055994530e-1f);
    p = fmaf(p, f, 1.0f);
    return __int_as_float(__float_as_int(p) + ((int)n << 23));
}
__device__ __forceinline__ int load_target(const void* tptr, int b, int C) {
    const int* p = (const int*)tptr;
    bool is64 = ((p[1] | p[3] | p[5] | p[7] | p[9]) == 0);
    long long t = is64 ? ((const long long*)tptr)[b] : (long long)p[b];
    if (t < 0) t = 0;
    if (t >= C) t = C - 1;
    return (int)t;
}

// Load 32 k-rows (chunk m) of B tile at col base c0 into buffer buf.
// Layout [k][n] bf16, row stride 528B, 16B-chunk XOR swizzle by (k>>3)&1.
__device__ __forceinline__ void load_B_chunk(const float* __restrict__ w,
                                             char* smem, int buf, int m,
                                             int c0, int C, int tid) {
    const float4* w4 = (const float4*)w;
    char* base = smem + SM_B + buf * BSZ;
    #pragma unroll
    for (int i = 0; i < 4; i++) {
        int idx = i * 512 + tid;              // 0..2047
        int k = m * 32 + (idx >> 6);          // tile-local k row
        int cq = idx & 63;
        int c = c0 + cq * 4;
        float4 v = make_float4(0.f, 0.f, 0.f, 0.f);
        if (c < C)                            // C % 4 == 0 -> all-or-nothing
            v = w4[((size_t)k * (size_t)C + (size_t)c) >> 2];
        uint2 pk;
        pk.x = pack_bf16x2(v.x, v.y);
        pk.y = pack_bf16x2(v.z, v.w);
        uint32_t byte = (uint32_t)(cq * 8) ^ (uint32_t)(((k >> 3) & 1) << 4);
        *(uint2*)(base + k * BSTRIDE + byte) = pk;
    }
}

// Load A chunk (128 rows starting at chunk*128) into buffer buf.
__device__ __forceinline__ void load_A_chunk(const float* __restrict__ feat,
                                             char* smem, int buf, int chunk,
                                             int tid) {
    const float4* f4 = (const float4*)feat;
    char* base = smem + SM_A + buf * ASZ;
    #pragma unroll
    for (int i = 0; i < 8; i++) {
        int idx = i * 512 + tid;              // 0..4095
        int r = idx >> 5, kq = idx & 31;
        float4 v = f4[(chunk * 128 + r) * 32 + kq];
        uint2 pk;
        pk.x = pack_bf16x2(v.x, v.y);
        pk.y = pack_bf16x2(v.z, v.w);
        *(uint2*)(base + r * ASTRIDE + kq * 8) = pk;
    }
}

// ================= persistent fused kernel =================
__global__ void __launch_bounds__(512, 1)
fused_kernel(const float* __restrict__ feat, const float* __restrict__ w,
             const void* __restrict__ target, int C, int NT) {
    extern __shared__ char smem[];
    const int tid  = threadIdx.x;
    const int wid  = tid >> 5;
    const int lane = tid & 31;
    const int bid  = blockIdx.x;
    const int wm   = wid >> 2;            // warp row group (32 rows)
    const int wn   = wid & 3;             // warp col group (64 cols)
    const uint32_t sb = smem_u32(smem);

    const int niter = (NT - bid + NCTA - 1) / NCTA;

    // ---- prologue: first B tile + A chunk 0 + aux ----
    #pragma unroll
    for (int m = 0; m < 4; m++)
        load_B_chunk(w, smem, 0, m, bid * BN, C, tid);
    load_A_chunk(feat, smem, 0, 0, tid);

    // aux: exact-fp32 target-column math, rows bid*4..bid*4+3 (CTAs 0..127)
    if (bid < 128 && wid < 4) {
        int b = bid * 4 + wid;
        int t = load_target(target, b, C);
        float fsq = 0.f, wsq = 0.f, dot = 0.f;
        #pragma unroll
        for (int q = 0; q < 4; q++) {
            int f = lane + q * 32;
            float fv = feat[b * FF + f];
            float wv = w[(size_t)f * (size_t)C + (size_t)t];
            fsq = fmaf(fv, fv, fsq);
            wsq = fmaf(wv, wv, wsq);
            dot = fmaf(fv, wv, dot);
        }
        const unsigned msk = 0xffffffffu;
        #pragma unroll
        for (int o = 16; o > 0; o >>= 1) {
            fsq += __shfl_down_sync(msk, fsq, o);
            wsq += __shfl_down_sync(msk, wsq, o);
            dot += __shfl_down_sync(msk, dot, o);
        }
        if (lane == 0) {
            float modulus = sqrtf(fsq) * sqrtf(wsq);
            float ct = dot / (modulus * 1.01f);
            ct = fminf(1.0f, fmaxf(-1.0f, ct));
            float ml = modulus * cosf(acosf(ct) + 0.5f);  // ANGLE=0.5
            g_margin[b] = ml;
            g_adj[b] = expf(ml) - expf(dot);
        }
    }
    __syncthreads();

    // per-lane ldmatrix bases (round-5 proven mapping)
    const uint32_t a_lb = (uint32_t)((wm * 32 + (lane & 15)) * ASTRIDE
                                     + ((lane >> 4) << 4));
    const uint32_t b_lb = (uint32_t)((((lane >> 3) & 1) * 8 + (lane & 7)) * BSTRIDE
                          + (((uint32_t)(wn * 128 + ((lane >> 4) << 4)))
                             ^ (uint32_t)(((lane >> 3) & 1) << 4)));

    int cur = 0;
    for (int it = 0; it < niter; it++) {
        const int bx = bid + it * NCTA;
        const bool have_next = (it + 1 < niter);
        const int nc0 = (bx + NCTA) * BN;

        for (int m = 0; m < 4; m++) {
            const bool last_all = (it == niter - 1) && (m == 3);
            if (!last_all)
                load_A_chunk(feat, smem, (m + 1) & 1, (m + 1) & 3, tid);
            if (have_next)
                load_B_chunk(w, smem, cur ^ 1, m, nc0, C, tid);

            const uint32_t abase = sb + SM_A + (m & 1) * ASZ;
            const uint32_t bbase = sb + SM_B + cur * BSZ;

            float acc[2][8][4];
            #pragma unroll
            for (int mi = 0; mi < 2; mi++)
                #pragma unroll
                for (int j = 0; j < 8; j++)
                    #pragma unroll
                    for (int q = 0; q < 4; q++) acc[mi][j][q] = 0.0f;

            #pragma unroll
            for (int ks = 0; ks < 8; ks++) {
                uint32_t a[2][4];
                ldsm4(a[0], abase + a_lb + ks * 32);
                ldsm4(a[1], abase + a_lb + 16 * ASTRIDE + ks * 32);
                #pragma unroll
                for (int np = 0; np < 4; np++) {
                    uint32_t bfr[4];
                    ldsm4t(bfr, bbase + b_lb + ks * 16 * BSTRIDE + np * 32);
                    #pragma unroll
                    for (int mi = 0; mi < 2; mi++) {
                        mma_bf16(acc[mi][np * 2 + 0], a[mi], bfr[0], bfr[1]);
                        mma_bf16(acc[mi][np * 2 + 1], a[mi], bfr[2], bfr[3]);
                    }
                }
            }

            // epilogue: all-FMA exp + warp row-sums -> direct STG, no barrier
            const unsigned msk = 0xffffffffu;
            float* slot = &g_part[(size_t)(bx * 4 + wn) * 512];
            #pragma unroll
            for (int mi = 0; mi < 2; mi++) {
                float s0 = 0.f, s1 = 0.f;
                #pragma unroll
                for (int j = 0; j < 8; j++) {
                    s0 += fast_exp(acc[mi][j][0]);
                    s0 += fast_exp(acc[mi][j][1]);
                    s1 += fast_exp(acc[mi][j][2]);
                    s1 += fast_exp(acc[mi][j][3]);
                }
                s0 += __shfl_xor_sync(msk, s0, 1);
                s0 += __shfl_xor_sync(msk, s0, 2);
                s1 += __shfl_xor_sync(msk, s1, 1);
                s1 += __shfl_xor_sync(msk, s1, 2);
                if ((lane & 3) == 0) {
                    int g = lane >> 2;
                    int grow = m * 128 + wm * 32 + mi * 16 + g;
                    slot[grow]     = s0;     // rows g..g+7 partial (64 cols)
                    slot[grow + 8] = s1;     // rows g+8..g+15 partial
                }
            }
            __syncthreads();                  // protect A/B buffers
        }
        cur ^= 1;
    }
}

// ================= finalize 1: per-row value =================
__global__ void finalize1_kernel(int NSLOT, float pad) {
    int row = blockIdx.x;        // 0..511
    int j = threadIdx.x;         // 0..127
    float s = 0.f;
    for (int t = j; t < NSLOT; t += 128)      // fixed order -> deterministic
        s += g_part[(size_t)t * 512 + row];
    __shared__ float red[128];
    red[j] = s;
    __syncthreads();
    #pragma unroll
    for (int o = 64; o > 0; o >>= 1) {
        if (j < o) red[j] += red[j + o];
        __syncthreads();
    }
    if (j == 0) {
        float down = red[0] - pad + g_adj[row];
        g_rowv[row] = logf(down) - g_margin[row];
    }
}

// ================= finalize 2: scalar =================
__global__ void finalize2_kernel(float* __restrict__ out) {
    int b = threadIdx.x;         // 0..511
    __shared__ float red[BB];
    red[b] = g_rowv[b];
    __syncthreads();
    #pragma unroll
    for (int o = BB / 2; o > 0; o >>= 1) {
        if (b < o) red[b] += red[b + o];
        __syncthreads();
    }
    if (b == 0) out[0] = red[0] / (float)BB;
}

// ================= launch =================
extern "C" void kernel_launch(void* const* d_in, const int* in_sizes, int n_in,
                              void* d_out, int out_size) {
    const float* feat = (const float*)d_in[0];
    const float* w    = (const float*)d_in[1];
    const void*  target = d_in[2];
    float* out = (float*)d_out;

    int C  = in_sizes[1] / FF;               // 100000
    int NT = (C + BN - 1) / BN;              // 391
    float pad = (float)(NT * BN - C);        // 96

    cudaFuncSetAttribute(fused_kernel,
                         cudaFuncAttributeMaxDynamicSharedMemorySize, SM_TOTAL);

    fused_kernel<<<NCTA, 512, SM_TOTAL>>>(feat, w, target, C, NT);
    finalize1_kernel<<<BB, 128>>>(4 * NT, pad);
    finalize2_kernel<<<1, BB>>>(out);
}

// round 8
// speedup vs baseline: 1.5836x; 1.1689x over previous
#include <cuda_runtime.h>
#include <cuda_bf16.h>
#include <math.h>
#include <stdint.h>

// ArcFace loss. B=512, F=128, C=100000.
// Persistent CTAs. A fragments live in REGISTERS for the whole kernel
// (each warp owns 32 fixed rows; 16 warps cover all 512). smem holds only a
// double-buffered B tile (BN=256). One barrier per tile. Hybrid MUFU/FMA exp.

#define FF 128
#define BB 512
#define BN 256
#define NCTA 148

__device__ float g_part[512 * 512];   // [tile][row]
__device__ float g_margin[BB];
__device__ float g_adj[BB];
__device__ float g_rowv[BB];

// smem: B 2x(128 k-rows x 528B)
#define BSTRIDE 528
#define BSZ     (128 * BSTRIDE)      // 67584
#define SM_B    0
#define SM_TOTAL (2 * BSZ)           // 135168  (also reused to stage A rows)
#define ASTRIDE 272                  // staging stride for A rows

__device__ __forceinline__ uint32_t smem_u32(const void* p) {
    uint32_t a;
    asm("{ .reg .u64 t; cvta.to.shared.u64 t, %1; cvt.u32.u64 %0, t; }"
        : "=r"(a) : "l"(p));
    return a;
}
__device__ __forceinline__ void ldsm4(uint32_t* r, uint32_t addr) {
    asm volatile("ldmatrix.sync.aligned.m8n8.x4.shared.b16 {%0,%1,%2,%3}, [%4];"
                 : "=r"(r[0]), "=r"(r[1]), "=r"(r[2]), "=r"(r[3]) : "r"(addr));
}
__device__ __forceinline__ void ldsm4t(uint32_t* r, uint32_t addr) {
    asm volatile("ldmatrix.sync.aligned.m8n8.x4.trans.shared.b16 {%0,%1,%2,%3}, [%4];"
                 : "=r"(r[0]), "=r"(r[1]), "=r"(r[2]), "=r"(r[3]) : "r"(addr));
}
__device__ __forceinline__ void mma_bf16(float* d, const uint32_t* a,
                                         uint32_t b0, uint32_t b1) {
    asm volatile(
        "mma.sync.aligned.m16n8k16.row.col.f32.bf16.bf16.f32 "
        "{%0,%1,%2,%3}, {%4,%5,%6,%7}, {%8,%9}, {%0,%1,%2,%3};"
        : "+f"(d[0]), "+f"(d[1]), "+f"(d[2]), "+f"(d[3])
        : "r"(a[0]), "r"(a[1]), "r"(a[2]), "r"(a[3]), "r"(b0), "r"(b1));
}
__device__ __forceinline__ uint32_t pack_bf16x2(float lo, float hi) {
    __nv_bfloat162 p = __floats2bfloat162_rn(lo, hi);
    return *(uint32_t*)&p;
}
// FMA-pipe exp (deg-6, exact at 0).
__device__ __forceinline__ float fast_exp(float x) {
    float z = x * 1.4426950408889634f;
    float n = rintf(z);
    float f = z - n;
    float p = 1.5403530393381606e-4f;
    p = fmaf(p, f, 1.3333558146428443e-3f);
    p = fmaf(p, f, 9.6181291076284770e-3f);
    p = fmaf(p, f, 5.5504108664821580e-2f);
    p = fmaf(p, f, 2.4022650695910070e-1f);
    p = fmaf(p, f, 6.9314718055994530e-1f);
    p = fmaf(p, f, 1.0f);
    return __int_as_float(__float_as_int(p) + ((int)n << 23));
}
__device__ __forceinline__ int load_target(const void* tptr, int b, int C) {
    const int* p = (const int*)tptr;
    bool is64 = ((p[1] | p[3] | p[5] | p[7] | p[9]) == 0);
    long long t = is64 ? ((const long long*)tptr)[b] : (long long)p[b];
    if (t < 0) t = 0;
    if (t >= C) t = C - 1;
    return (int)t;
}

// Load 32 k-rows (chunk m) of B tile at col base c0 into buffer buf.
// Layout [k][n] bf16, stride 528B, 16B-chunk XOR swizzle by (k>>3)&1. (R5-proven)
__device__ __forceinline__ void load_B_chunk(const float* __restrict__ w,
                                             char* smem, int buf, int m,
                                             int c0, int C, int tid) {
    const float4* w4 = (const float4*)w;
    char* base = smem + SM_B + buf * BSZ;
    #pragma unroll
    for (int i = 0; i < 4; i++) {
        int idx = i * 512 + tid;              // 0..2047
        int k = m * 32 + (idx >> 6);
        int cq = idx & 63;
        int c = c0 + cq * 4;
        float4 v = make_float4(0.f, 0.f, 0.f, 0.f);
        if (c < C)                            // C % 4 == 0 -> all-or-nothing
            v = w4[((size_t)k * (size_t)C + (size_t)c) >> 2];
        uint2 pk;
        pk.x = pack_bf16x2(v.x, v.y);
        pk.y = pack_bf16x2(v.z, v.w);
        uint32_t byte = (uint32_t)(cq * 8) ^ (uint32_t)(((k >> 3) & 1) << 4);
        *(uint2*)(base + k * BSTRIDE + byte) = pk;
    }
}

// ================= persistent fused kernel =================
__global__ void __launch_bounds__(512, 1)
fused_kernel(const float* __restrict__ feat, const float* __restrict__ w,
             const void* __restrict__ target, int C, int NT) {
    extern __shared__ char smem[];
    const int tid  = threadIdx.x;
    const int wid  = tid >> 5;            // warp owns rows wid*32..wid*32+31
    const int lane = tid & 31;
    const int bid  = blockIdx.x;
    const uint32_t sb = smem_u32(smem);

    const int niter = (NT - bid + NCTA - 1) / NCTA;

    // ---- aux: exact-fp32 target-column math (CTAs 0..127, 4 warps) ----
    if (bid < 128 && wid < 4) {
        int b = bid * 4 + wid;
        int t = load_target(target, b, C);
        float fsq = 0.f, wsq = 0.f, dot = 0.f;
        #pragma unroll
        for (int q = 0; q < 4; q++) {
            int f = lane + q * 32;
            float fv = feat[b * FF + f];
            float wv = w[(size_t)f * (size_t)C + (size_t)t];
            fsq = fmaf(fv, fv, fsq);
            wsq = fmaf(wv, wv, wsq);
            dot = fmaf(fv, wv, dot);
        }
        const unsigned msk = 0xffffffffu;
        #pragma unroll
        for (int o = 16; o > 0; o >>= 1) {
            fsq += __shfl_down_sync(msk, fsq, o);
            wsq += __shfl_down_sync(msk, wsq, o);
            dot += __shfl_down_sync(msk, dot, o);
        }
        if (lane == 0) {
            float modulus = sqrtf(fsq) * sqrtf(wsq);
            float ct = dot / (modulus * 1.01f);
            ct = fminf(1.0f, fmaxf(-1.0f, ct));
            float ml = modulus * cosf(acosf(ct) + 0.5f);  // ANGLE=0.5
            g_margin[b] = ml;
            g_adj[b] = expf(ml) - expf(dot);
        }
    }

    // ---- stage A and capture per-warp fragments in registers ----
    uint32_t afrag[2][8][4];              // [mi][ks][q] : rows wid*32.., K=128
    {
        const float4* f4 = (const float4*)feat;
        #pragma unroll
        for (int round = 0; round < 2; round++) {
            __syncthreads();
            // stage rows round*256 .. round*256+255 at smem base (272B stride)
            #pragma unroll
            for (int i = 0; i < 16; i++) {
                int idx = i * 512 + tid;          // 0..8191
                int r = idx >> 5, kq = idx & 31;
                float4 v = f4[(round * 256 + r) * 32 + kq];
                uint2 pk;
                pk.x = pack_bf16x2(v.x, v.y);
                pk.y = pack_bf16x2(v.z, v.w);
                *(uint2*)(smem + r * ASTRIDE + kq * 8) = pk;
            }
            __syncthreads();
            if ((wid >> 3) == round) {
                uint32_t a_lb = (uint32_t)(((wid & 7) * 32 + (lane & 15)) * ASTRIDE
                                           + ((lane >> 4) << 4));
                #pragma unroll
                for (int mi = 0; mi < 2; mi++)
                    #pragma unroll
                    for (int ks = 0; ks < 8; ks++)
                        ldsm4(afrag[mi][ks],
                              sb + a_lb + mi * 16 * ASTRIDE + ks * 32);
            }
        }
    }
    __syncthreads();

    // ---- first B tile ----
    #pragma unroll
    for (int m = 0; m < 4; m++)
        load_B_chunk(w, smem, 0, m, bid * BN, C, tid);
    __syncthreads();

    // B fragment lane base (R5-proven mapping; col-group offset added per cg)
    const uint32_t b_lb0 = (uint32_t)((((lane >> 3) & 1) * 8 + (lane & 7)) * BSTRIDE
                           + ((uint32_t)((lane >> 4) << 4)
                              ^ (uint32_t)(((lane >> 3) & 1) << 4)));

    int cur = 0;
    for (int it = 0; it < niter; it++) {
        const int bx = bid + it * NCTA;
        const bool have_next = (it + 1 < niter);
        const int nc0 = (bx + NCTA) * BN;
        const uint32_t bbase = sb + SM_B + cur * BSZ;

        float rs[2][2] = {{0.f, 0.f}, {0.f, 0.f}};   // [mi][row-half] sums

        for (int cg = 0; cg < 4; cg++) {             // 64-col groups
            if (have_next)                            // spread next-tile load
                load_B_chunk(w, smem, cur ^ 1, cg, nc0, C, tid);

            float acc[2][8][4];
            #pragma unroll
            for (int mi = 0; mi < 2; mi++)
                #pragma unroll
                for (int j = 0; j < 8; j++)
                    #pragma unroll
                    for (int q = 0; q < 4; q++) acc[mi][j][q] = 0.0f;

            const uint32_t b_cg = b_lb0 + (uint32_t)(cg * 128);
            #pragma unroll
            for (int ks = 0; ks < 8; ks++) {
                #pragma unroll
                for (int np = 0; np < 4; np++) {
                    uint32_t bfr[4];
                    ldsm4t(bfr, bbase + b_cg + ks * 16 * BSTRIDE + np * 32);
                    mma_bf16(acc[0][np * 2 + 0], afrag[0][ks], bfr[0], bfr[1]);
                    mma_bf16(acc[0][np * 2 + 1], afrag[0][ks], bfr[2], bfr[3]);
                    mma_bf16(acc[1][np * 2 + 0], afrag[1][ks], bfr[0], bfr[1]);
                    mma_bf16(acc[1][np * 2 + 1], afrag[1][ks], bfr[2], bfr[3]);
                }
            }

            // hybrid exp + col-quad shfl reduce; accumulate across cg in regs
            const unsigned msk = 0xffffffffu;
            #pragma unroll
            for (int mi = 0; mi < 2; mi++) {
                float s0 = 0.f, s1 = 0.f;
                #pragma unroll
                for (int j = 0; j < 8; j++) {
                    s0 += __expf(acc[mi][j][0]);      // MUFU half
                    s0 += fast_exp(acc[mi][j][1]);    // FMA half
                    s1 += __expf(acc[mi][j][2]);
                    s1 += fast_exp(acc[mi][j][3]);
                }
                s0 += __shfl_xor_sync(msk, s0, 1);
                s0 += __shfl_xor_sync(msk, s0, 2);
                s1 += __shfl_xor_sync(msk, s1, 1);
                s1 += __shfl_xor_sync(msk, s1, 2);
                rs[mi][0] += s0;
                rs[mi][1] += s1;
            }
        }

        // one STG burst per tile: rows wid*32 + {g, g+8, g+16, g+24}
        if ((lane & 3) == 0) {
            int g = lane >> 2;
            float* slot = &g_part[(size_t)bx * 512 + wid * 32];
            slot[g]      = rs[0][0];
            slot[g + 8]  = rs[0][1];
            slot[g + 16] = rs[1][0];
            slot[g + 24] = rs[1][1];
        }
        __syncthreads();                  // B buffer swap protection
        cur ^= 1;
    }
}

// ================= finalize 1: per-row value =================
__global__ void finalize1_kernel(int NT, float pad) {
    int row = blockIdx.x;        // 0..511
    int j = threadIdx.x;         // 0..127
    float s = 0.f;
    for (int t = j; t < NT; t += 128)         // fixed order -> deterministic
        s += g_part[(size_t)t * 512 + row];
    __shared__ float red[128];
    red[j] = s;
    __syncthreads();
    #pragma unroll
    for (int o = 64; o > 0; o >>= 1) {
        if (j < o) red[j] += red[j + o];
        __syncthreads();
    }
    if (j == 0) {
        float down = red[0] - pad + g_adj[row];
        g_rowv[row] = logf(down) - g_margin[row];
    }
}

// ================= finalize 2: scalar =================
__global__ void finalize2_kernel(float* __restrict__ out) {
    int b = threadIdx.x;         // 0..511
    __shared__ float red[BB];
    red[b] = g_rowv[b];
    __syncthreads();
    #pragma unroll
    for (int o = BB / 2; o > 0; o >>= 1) {
        if (b < o) red[b] += red[b + o];
        __syncthreads();
    }
    if (b == 0) out[0] = red[0] / (float)BB;
}

// ================= launch =================
extern "C" void kernel_launch(void* const* d_in, const int* in_sizes, int n_in,
                              void* d_out, int out_size) {
    const float* feat = (const float*)d_in[0];
    const float* w    = (const float*)d_in[1];
    const void*  target = d_in[2];
    float* out = (float*)d_out;

    int C  = in_sizes[1] / FF;               // 100000
    int NT = (C + BN - 1) / BN;              // 391
    float pad = (float)(NT * BN - C);        // 96

    cudaFuncSetAttribute(fused_kernel,
                         cudaFuncAttributeMaxDynamicSharedMemorySize, SM_TOTAL);

    fused_kernel<<<NCTA, 512, SM_TOTAL>>>(feat, w, target, C, NT);
    finalize1_kernel<<<BB, 128>>>(NT, pad);
    finalize2_kernel<<<1, BB>>>(out);
}

// round 10
// speedup vs baseline: 1.7288x; 1.0917x over previous
#include <cuda_runtime.h>
#include <cuda_bf16.h>
#include <math.h>
#include <stdint.h>

// ArcFace loss. B=512, F=128, C=100000.
// R5 skeleton + (1) A as fragment-permuted bf16 in gmem (LDG.128 per frag,
// L1-resident, no smem/no per-m-iter barrier), (2) B loads pipelined through
// registers (LDG before MMA, convert+STS after), (3) smem = B double buffer only.
// R9 bug fixed: fused-kernel A indexing used strides 2x the packed layout
// (m*4096/wm*1024 vs actual m*2048/wm*512) -> OOB reads -> inf.

#define FF 128
#define BB 512
#define BN 256
#define NCTA 148

__device__ float g_part[1600 * 512];  // [slot = bx*4 + wn][row]
__device__ float g_margin[BB];
__device__ float g_adj[BB];
__device__ float g_rowv[BB];
__device__ uint4 g_Apack[8192];       // permuted bf16 A fragments (128KB)

// smem: B 2x(128 k-rows x 528B)
#define BSTRIDE 528
#define BSZ     (128 * BSTRIDE)      // 67584
#define SM_B    0
#define SM_TOTAL (2 * BSZ)           // 135168

__device__ __forceinline__ uint32_t smem_u32(const void* p) {
    uint32_t a;
    asm("{ .reg .u64 t; cvta.to.shared.u64 t, %1; cvt.u32.u64 %0, t; }"
        : "=r"(a) : "l"(p));
    return a;
}
__device__ __forceinline__ void ldsm4t(uint32_t* r, uint32_t addr) {
    asm volatile("ldmatrix.sync.aligned.m8n8.x4.trans.shared.b16 {%0,%1,%2,%3}, [%4];"
                 : "=r"(r[0]), "=r"(r[1]), "=r"(r[2]), "=r"(r[3]) : "r"(addr));
}
__device__ __forceinline__ void mma4(float* d, uint32_t a0, uint32_t a1,
                                     uint32_t a2, uint32_t a3,
                                     uint32_t b0, uint32_t b1) {
    asm volatile(
        "mma.sync.aligned.m16n8k16.row.col.f32.bf16.bf16.f32 "
        "{%0,%1,%2,%3}, {%4,%5,%6,%7}, {%8,%9}, {%0,%1,%2,%3};"
        : "+f"(d[0]), "+f"(d[1]), "+f"(d[2]), "+f"(d[3])
        : "r"(a0), "r"(a1), "r"(a2), "r"(a3), "r"(b0), "r"(b1));
}
__device__ __forceinline__ uint32_t pack_bf16x2(float lo, float hi) {
    __nv_bfloat162 p = __floats2bfloat162_rn(lo, hi);
    return *(uint32_t*)&p;
}
// FMA-pipe exp (deg-6, exact at 0).
__device__ __forceinline__ float fast_exp(float x) {
    float z = x * 1.4426950408889634f;
    float n = rintf(z);
    float f = z - n;
    float p = 1.5403530393381606e-4f;
    p = fmaf(p, f, 1.3333558146428443e-3f);
    p = fmaf(p, f, 9.6181291076284770e-3f);
    p = fmaf(p, f, 5.5504108664821580e-2f);
    p = fmaf(p, f, 2.4022650695910070e-1f);
    p = fmaf(p, f, 6.9314718055994530e-1f);
    p = fmaf(p, f, 1.0f);
    return __int_as_float(__float_as_int(p) + ((int)n << 23));
}
__device__ __forceinline__ int load_target(const void* tptr, int b, int C) {
    const int* p = (const int*)tptr;
    bool is64 = ((p[1] | p[3] | p[5] | p[7] | p[9]) == 0);
    long long t = is64 ? ((const long long*)tptr)[b] : (long long)p[b];
    if (t < 0) t = 0;
    if (t >= C) t = C - 1;
    return (int)t;
}

// ======== pre-kernel: A -> fragment-permuted bf16 ========
// quad index i = mc*2048 + wm*512 + mi*256 + ks*32 + lane   (8192 quads)
// holds {a0,a1,a2,a3} for m16n8k16.row A fragment:
//   r0 = mc*128 + wm*32 + mi*16 + lane/4, r1 = r0+8, kb = ks*16 + (lane%4)*2
//   a0=(r0,kb..kb+1) a1=(r1,kb..) a2=(r0,kb+8..) a3=(r1,kb+8..)
__global__ void precvt_A(const float* __restrict__ feat) {
    int i = blockIdx.x * 256 + threadIdx.x;     // 0..8191
    int lane = i & 31, ks = (i >> 5) & 7, mi = (i >> 8) & 1;
    int wm = (i >> 9) & 3, mc = (i >> 11) & 3;
    int r0 = mc * 128 + wm * 32 + mi * 16 + (lane >> 2);
    int r1 = r0 + 8;
    int kb = ks * 16 + (lane & 3) * 2;
    uint4 q;
    q.x = pack_bf16x2(feat[r0 * FF + kb],     feat[r0 * FF + kb + 1]);
    q.y = pack_bf16x2(feat[r1 * FF + kb],     feat[r1 * FF + kb + 1]);
    q.z = pack_bf16x2(feat[r0 * FF + kb + 8], feat[r0 * FF + kb + 9]);
    q.w = pack_bf16x2(feat[r1 * FF + kb + 8], feat[r1 * FF + kb + 9]);
    g_Apack[i] = q;
}

// ======== B chunk: split LDG / STS (pipelined through registers) ========
__device__ __forceinline__ void ldg_B(float4* vh, const float* __restrict__ w,
                                      int m, int c0, int C, int tid) {
    const float4* w4 = (const float4*)w;
    #pragma unroll
    for (int i = 0; i < 4; i++) {
        int idx = i * 512 + tid;
        int k = m * 32 + (idx >> 6);
        int c = c0 + (idx & 63) * 4;
        vh[i] = make_float4(0.f, 0.f, 0.f, 0.f);
        if (c < C)                            // C % 4 == 0 -> all-or-nothing
            vh[i] = w4[((size_t)k * (size_t)C + (size_t)c) >> 2];
    }
}
__device__ __forceinline__ void sts_B(const float4* vh, char* smem, int buf,
                                      int m, int tid) {
    char* base = smem + SM_B + buf * BSZ;
    #pragma unroll
    for (int i = 0; i < 4; i++) {
        int idx = i * 512 + tid;
        int k = m * 32 + (idx >> 6);
        int cq = idx & 63;
        uint2 pk;
        pk.x = pack_bf16x2(vh[i].x, vh[i].y);
        pk.y = pack_bf16x2(vh[i].z, vh[i].w);
        uint32_t byte = (uint32_t)(cq * 8) ^ (uint32_t)(((k >> 3) & 1) << 4);
        *(uint2*)(base + k * BSTRIDE + byte) = pk;
    }
}

// ================= persistent fused kernel =================
__global__ void __launch_bounds__(512, 1)
fused_kernel(const float* __restrict__ feat, const float* __restrict__ w,
             const void* __restrict__ target, int C, int NT) {
    extern __shared__ char smem[];
    const int tid  = threadIdx.x;
    const int wid  = tid >> 5;
    const int lane = tid & 31;
    const int bid  = blockIdx.x;
    const int wm   = wid >> 2;            // warp row group (32 rows in m-chunk)
    const int wn   = wid & 3;             // warp col group (64 cols)
    const uint32_t sb = smem_u32(smem);

    const int niter = (NT - bid + NCTA - 1) / NCTA;

    // ---- prologue: first B tile (fused ldg+sts) + aux ----
    {
        float4 vh[4];
        #pragma unroll
        for (int m = 0; m < 4; m++) {
            ldg_B(vh, w, m, bid * BN, C, tid);
            sts_B(vh, smem, 0, m, tid);
        }
    }
    // aux: exact-fp32 target-column math (CTAs 0..127, 4 warps each)
    if (bid < 128 && wid < 4) {
        int b = bid * 4 + wid;
        int t = load_target(target, b, C);
        float fsq = 0.f, wsq = 0.f, dot = 0.f;
        #pragma unroll
        for (int q = 0; q < 4; q++) {
            int f = lane + q * 32;
            float fv = feat[b * FF + f];
            float wv = w[(size_t)f * (size_t)C + (size_t)t];
            fsq = fmaf(fv, fv, fsq);
            wsq = fmaf(wv, wv, wsq);
            dot = fmaf(fv, wv, dot);
        }
        const unsigned msk = 0xffffffffu;
        #pragma unroll
        for (int o = 16; o > 0; o >>= 1) {
            fsq += __shfl_down_sync(msk, fsq, o);
            wsq += __shfl_down_sync(msk, wsq, o);
            dot += __shfl_down_sync(msk, dot, o);
        }
        if (lane == 0) {
            float modulus = sqrtf(fsq) * sqrtf(wsq);
            float ct = dot / (modulus * 1.01f);
            ct = fminf(1.0f, fmaxf(-1.0f, ct));
            float ml = modulus * cosf(acosf(ct) + 0.5f);  // ANGLE=0.5
            g_margin[b] = ml;
            g_adj[b] = expf(ml) - expf(dot);
        }
    }
    __syncthreads();

    // B fragment lane base (R5-proven mapping)
    const uint32_t b_lb = (uint32_t)((((lane >> 3) & 1) * 8 + (lane & 7)) * BSTRIDE
                          + (((uint32_t)(wn * 128 + ((lane >> 4) << 4)))
                             ^ (uint32_t)(((lane >> 3) & 1) << 4)));

    const uint4* __restrict__ Ap = g_Apack;

    int cur = 0;
    for (int it = 0; it < niter; it++) {
        const int bx = bid + it * NCTA;
        const bool have_next = (it + 1 < niter);
        const int nc0 = (bx + NCTA) * BN;
        const uint32_t bbase = sb + SM_B + cur * BSZ;

        for (int m = 0; m < 4; m++) {
            float4 vh[4];
            if (have_next)
                ldg_B(vh, w, m, nc0, C, tid);    // LDG early: lands behind MMA

            // A fragment quad base (matches precvt layout: mc*2048+wm*512+...)
            const int qb = m * 2048 + wm * 512 + lane;

            float acc[2][8][4];
            #pragma unroll
            for (int mi = 0; mi < 2; mi++)
                #pragma unroll
                for (int j = 0; j < 8; j++)
                    #pragma unroll
                    for (int q = 0; q < 4; q++) acc[mi][j][q] = 0.0f;

            #pragma unroll
            for (int ks = 0; ks < 8; ks++) {
                uint4 af0 = Ap[qb + ks * 32];         // mi=0 fragment quad
                uint4 af1 = Ap[qb + 256 + ks * 32];   // mi=1 fragment quad
                #pragma unroll
                for (int np = 0; np < 4; np++) {
                    uint32_t bfr[4];
                    ldsm4t(bfr, bbase + b_lb + ks * 16 * BSTRIDE + np * 32);
                    mma4(acc[0][np * 2 + 0], af0.x, af0.y, af0.z, af0.w, bfr[0], bfr[1]);
                    mma4(acc[0][np * 2 + 1], af0.x, af0.y, af0.z, af0.w, bfr[2], bfr[3]);
                    mma4(acc[1][np * 2 + 0], af1.x, af1.y, af1.z, af1.w, bfr[0], bfr[1]);
                    mma4(acc[1][np * 2 + 1], af1.x, af1.y, af1.z, af1.w, bfr[2], bfr[3]);
                }
            }

            // epilogue: hybrid exp + warp row-sums -> direct STG
            const unsigned msk = 0xffffffffu;
            float* slot = &g_part[(size_t)(bx * 4 + wn) * 512];
            #pragma unroll
            for (int mi = 0; mi < 2; mi++) {
                float s0 = 0.f, s1 = 0.f;
                #pragma unroll
                for (int j = 0; j < 8; j++) {
                    s0 += __expf(acc[mi][j][0]);      // MUFU half
                    s0 += fast_exp(acc[mi][j][1]);    // FMA half
                    s1 += __expf(acc[mi][j][2]);
                    s1 += fast_exp(acc[mi][j][3]);
                }
                s0 += __shfl_xor_sync(msk, s0, 1);
                s0 += __shfl_xor_sync(msk, s0, 2);
                s1 += __shfl_xor_sync(msk, s1, 1);
                s1 += __shfl_xor_sync(msk, s1, 2);
                if ((lane & 3) == 0) {
                    int g = lane >> 2;
                    int grow = m * 128 + wm * 32 + mi * 16 + g;
                    slot[grow]     = s0;
                    slot[grow + 8] = s1;
                }
            }

            if (have_next)
                sts_B(vh, smem, cur ^ 1, m, tid);    // STS late: data long arrived
        }
        __syncthreads();                  // ONE barrier per tile (B swap)
        cur ^= 1;
    }
}

// ================= finalize 1: per-row value =================
__global__ void finalize1_kernel(int NSLOT, float pad) {
    int row = blockIdx.x;        // 0..511
    int j = threadIdx.x;         // 0..127
    float s = 0.f;
    for (int t = j; t < NSLOT; t += 128)      // fixed order -> deterministic
        s += g_part[(size_t)t * 512 + row];
    __shared__ float red[128];
    red[j] = s;
    __syncthreads();
    #pragma unroll
    for (int o = 64; o > 0; o >>= 1) {
        if (j < o) red[j] += red[j + o];
        __syncthreads();
    }
    if (j == 0) {
        float down = red[0] - pad + g_adj[row];
        g_rowv[row] = logf(down) - g_margin[row];
    }
}

// ================= finalize 2: scalar =================
__global__ void finalize2_kernel(float* __restrict__ out) {
    int b = threadIdx.x;         // 0..511
    __shared__ float red[BB];
    red[b] = g_rowv[b];
    __syncthreads();
    #pragma unroll
    for (int o = BB / 2; o > 0; o >>= 1) {
        if (b < o) red[b] += red[b + o];
        __syncthreads();
    }
    if (b == 0) out[0] = red[0] / (float)BB;
}

// ================= launch =================
extern "C" void kernel_launch(void* const* d_in, const int* in_sizes, int n_in,
                              void* d_out, int out_size) {
    const float* feat = (const float*)d_in[0];
    const float* w    = (const float*)d_in[1];
    const void*  target = d_in[2];
    float* out = (float*)d_out;

    int C  = in_sizes[1] / FF;               // 100000
    int NT = (C + BN - 1) / BN;              // 391
    float pad = (float)(NT * BN - C);        // 96

    cudaFuncSetAttribute(fused_kernel,
                         cudaFuncAttributeMaxDynamicSharedMemorySize, SM_TOTAL);

    precvt_A<<<32, 256>>>(feat);
    fused_kernel<<<NCTA, 512, SM_TOTAL>>>(feat, w, target, C, NT);
    finalize1_kernel<<<BB, 128>>>(4 * NT, pad);
    finalize2_kernel<<<1, BB>>>(out);
}